// round 2
// baseline (speedup 1.0000x reference)
#include <cuda_runtime.h>
#include <cstdint>

#define L       320
#define D       128
#define H       4
#define DH      32
#define NROW    (L*L)          // 102400
#define SCALE   0.17677669529663687f   // 1/sqrt(32)

// ---------------- scratch (static device memory, no allocation) ----------------
__device__ float g_x   [NROW * D];   // layernormed pair
__device__ float g_q   [NROW * D];   // [i][h][j][d]  (pre-scaled by 1/sqrt(Dh))
__device__ float g_k   [NROW * D];   // [i][h][j][d]
__device__ float g_v   [NROW * D];   // [i][h][j][d]
__device__ float g_g   [NROW * D];   // row layout [(i*L+j)*D + h*32+d], sigmoid applied
__device__ float g_o   [NROW * D];   // gated attention output, row layout
__device__ float g_bias[L * H * L];  // [i][h][j]

// ================= kernel 1: layernorm + bias projection =================
// one block per pair row (i,j), 128 threads
__global__ void k_ln_bias(const float* __restrict__ pair,
                          const float* __restrict__ nw,
                          const float* __restrict__ nb,
                          const float* __restrict__ Wb) {
    int row = blockIdx.x;           // i*L + j
    int t   = threadIdx.x;          // 0..127
    int w   = t >> 5, lane = t & 31;

    float p = pair[(size_t)row * D + t];

    __shared__ float px[D];
    __shared__ float rs[4], rs2[4];
    px[t] = p;

    float s = p, s2 = p * p;
    #pragma unroll
    for (int o = 16; o > 0; o >>= 1) {
        s  += __shfl_xor_sync(0xffffffffu, s,  o);
        s2 += __shfl_xor_sync(0xffffffffu, s2, o);
    }
    if (lane == 0) { rs[w] = s; rs2[w] = s2; }
    __syncthreads();

    float mean = (rs[0] + rs[1] + rs[2] + rs[3]) * (1.0f / 128.0f);
    float var  = (rs2[0] + rs2[1] + rs2[2] + rs2[3]) * (1.0f / 128.0f) - mean * mean;
    float inv  = rsqrtf(var + 1e-5f);
    g_x[(size_t)row * D + t] = (p - mean) * inv * nw[t] + nb[t];

    // bias: head w computed by warp w (dot of raw pair row with Wb[w])
    const float* wb = Wb + w * D;
    float bv = px[lane]      * wb[lane]
             + px[lane + 32] * wb[lane + 32]
             + px[lane + 64] * wb[lane + 64]
             + px[lane + 96] * wb[lane + 96];
    #pragma unroll
    for (int o = 16; o > 0; o >>= 1)
        bv += __shfl_xor_sync(0xffffffffu, bv, o);
    if (lane == 0) {
        int i = row / L, j = row % L;
        g_bias[(i * H + w) * L + j] = bv;
    }
}

// ================= kernel 2: Q/K/V/G projections =================
// block = 64 rows of x, 256 threads; W held transposed in shared
__global__ __launch_bounds__(256) void k_proj(const float* __restrict__ Wq,
                                              const float* __restrict__ Wk,
                                              const float* __restrict__ Wv,
                                              const float* __restrict__ Wg,
                                              const float* __restrict__ bg) {
    __shared__ float xs[64 * 128];
    __shared__ float Ws[128 * 129];
    int t = threadIdx.x;
    int base = blockIdx.x * 64;     // global row base

    for (int idx = t; idx < 64 * 128; idx += 256)
        xs[idx] = g_x[(size_t)base * 128 + idx];

    int ty = t >> 5, tx = t & 31;

    for (int m = 0; m < 4; m++) {
        const float* W = (m == 0) ? Wq : (m == 1) ? Wk : (m == 2) ? Wv : Wg;
        __syncthreads();
        for (int idx = t; idx < 128 * 128; idx += 256) {
            int c = idx >> 7, k = idx & 127;
            Ws[k * 129 + c] = W[idx];
        }
        __syncthreads();

        float acc[8][4];
        #pragma unroll
        for (int r = 0; r < 8; r++)
            #pragma unroll
            for (int cc = 0; cc < 4; cc++) acc[r][cc] = 0.0f;

        #pragma unroll 4
        for (int k = 0; k < 128; k++) {
            float wv0 = Ws[k * 129 + tx];
            float wv1 = Ws[k * 129 + tx + 32];
            float wv2 = Ws[k * 129 + tx + 64];
            float wv3 = Ws[k * 129 + tx + 96];
            #pragma unroll
            for (int r = 0; r < 8; r++) {
                float xv = xs[(ty * 8 + r) * 128 + k];
                acc[r][0] += xv * wv0;
                acc[r][1] += xv * wv1;
                acc[r][2] += xv * wv2;
                acc[r][3] += xv * wv3;
            }
        }

        #pragma unroll
        for (int r = 0; r < 8; r++) {
            int R = base + ty * 8 + r;
            int i = R / L, j = R % L;
            if (m < 3) {
                float* dst = (m == 0) ? g_q : (m == 1) ? g_k : g_v;
                float sc = (m == 0) ? SCALE : 1.0f;
                #pragma unroll
                for (int cc = 0; cc < 4; cc++)   // head = cc, d = tx
                    dst[(((size_t)i * H + cc) * L + j) * DH + tx] = acc[r][cc] * sc;
            } else {
                #pragma unroll
                for (int cc = 0; cc < 4; cc++) {
                    int c = cc * 32 + tx;
                    float v = acc[r][cc] + bg[c];
                    g_g[(size_t)R * D + c] = 1.0f / (1.0f + __expf(-v));
                }
            }
        }
    }
}

// ================= kernel 3: attention per (row i, head h) =================
// 256 threads; K,V,bias in shared; each warp processes query rows in pairs
#define KS_OFF 0
#define VS_OFF (KS_OFF + 320 * 33)
#define PS_OFF (VS_OFF + 320 * 33)     // 8 warps * 2 rows * 320
#define BS_OFF (PS_OFF + 8 * 640)
#define QS_OFF (BS_OFF + 320)          // 8 warps * 64
#define SM3_FLOATS (QS_OFF + 8 * 64)   // 27072 floats = 108288 bytes

__global__ __launch_bounds__(256) void k_attn() {
    extern __shared__ float sm[];
    float* Ks = sm + KS_OFF;
    float* Vs = sm + VS_OFF;
    float* Ps = sm + PS_OFF;
    float* Bs = sm + BS_OFF;
    float* Qs = sm + QS_OFF;

    int blk = blockIdx.x;
    int i = blk >> 2, h = blk & 3;
    int t = threadIdx.x, w = t >> 5, lane = t & 31;

    const float* Kg = g_k + ((size_t)i * H + h) * L * DH;
    const float* Vg = g_v + ((size_t)i * H + h) * L * DH;
    const float* Qg = g_q + ((size_t)i * H + h) * L * DH;

    for (int idx = t; idx < L * DH; idx += 256) {
        int j = idx >> 5, d = idx & 31;
        Ks[j * 33 + d] = Kg[idx];
        Vs[j * 33 + d] = Vg[idx];
    }
    for (int idx = t; idx < L; idx += 256)
        Bs[idx] = g_bias[(i * H + h) * L + idx];
    __syncthreads();

    float* Pw = Ps + w * 640;
    float* Qw = Qs + w * 64;

    // warp w handles contiguous rows [w*40, w*40+40), in pairs
    for (int pr = 0; pr < 20; pr++) {
        int qa = w * 40 + pr * 2;
        int qb = qa + 1;

        Qw[lane]      = Qg[qa * DH + lane];
        Qw[32 + lane] = Qg[qb * DH + lane];
        __syncwarp();

        float ra[32], rb[32];
        #pragma unroll
        for (int d = 0; d < 32; d++) { ra[d] = Qw[d]; rb[d] = Qw[32 + d]; }

        float sa[10], sb[10];
        #pragma unroll
        for (int jj = 0; jj < 10; jj++) {
            int j = jj * 32 + lane;
            float va = 0.0f, vb = 0.0f;
            const float* kr = Ks + j * 33;
            #pragma unroll
            for (int d = 0; d < 32; d++) {
                float kv = kr[d];
                va += ra[d] * kv;
                vb += rb[d] * kv;
            }
            float bsv = Bs[j];
            sa[jj] = va + bsv;
            sb[jj] = vb + bsv;
        }

        // softmax (rows independent)
        float ma = sa[0], mb = sb[0];
        #pragma unroll
        for (int jj = 1; jj < 10; jj++) { ma = fmaxf(ma, sa[jj]); mb = fmaxf(mb, sb[jj]); }
        #pragma unroll
        for (int o = 16; o > 0; o >>= 1) {
            ma = fmaxf(ma, __shfl_xor_sync(0xffffffffu, ma, o));
            mb = fmaxf(mb, __shfl_xor_sync(0xffffffffu, mb, o));
        }
        float suma = 0.0f, sumb = 0.0f;
        #pragma unroll
        for (int jj = 0; jj < 10; jj++) {
            float ea = __expf(sa[jj] - ma);
            float eb = __expf(sb[jj] - mb);
            suma += ea; sumb += eb;
            Pw[jj * 32 + lane]       = ea;
            Pw[320 + jj * 32 + lane] = eb;
        }
        #pragma unroll
        for (int o = 16; o > 0; o >>= 1) {
            suma += __shfl_xor_sync(0xffffffffu, suma, o);
            sumb += __shfl_xor_sync(0xffffffffu, sumb, o);
        }
        __syncwarp();

        // out[d=lane] = sum_j p_j * V[j][lane]
        float aa = 0.0f, ab = 0.0f;
        #pragma unroll 4
        for (int j = 0; j < 320; j++) {
            float vv = Vs[j * 33 + lane];
            aa += Pw[j] * vv;
            ab += Pw[320 + j] * vv;
        }
        aa /= suma;
        ab /= sumb;

        size_t Ra = (size_t)i * L + qa;
        size_t Rb = (size_t)i * L + qb;
        int c = h * 32 + lane;
        g_o[Ra * D + c] = aa * g_g[Ra * D + c];
        g_o[Rb * D + c] = ab * g_g[Rb * D + c];
        __syncwarp();   // protect Qw/Pw before next pair overwrites
    }
}

// ================= kernel 4: output projection + residual =================
__global__ __launch_bounds__(256) void k_out(const float* __restrict__ Wo,
                                             const float* __restrict__ bo,
                                             const float* __restrict__ pair,
                                             float* __restrict__ out) {
    __shared__ float xs[64 * 128];
    __shared__ float Ws[128 * 129];
    int t = threadIdx.x;
    int base = blockIdx.x * 64;

    for (int idx = t; idx < 64 * 128; idx += 256)
        xs[idx] = g_o[(size_t)base * 128 + idx];
    for (int idx = t; idx < 128 * 128; idx += 256) {
        int c = idx >> 7, k = idx & 127;
        Ws[k * 129 + c] = Wo[idx];
    }
    __syncthreads();

    int ty = t >> 5, tx = t & 31;
    float acc[8][4];
    #pragma unroll
    for (int r = 0; r < 8; r++)
        #pragma unroll
        for (int cc = 0; cc < 4; cc++) acc[r][cc] = 0.0f;

    #pragma unroll 4
    for (int k = 0; k < 128; k++) {
        float wv0 = Ws[k * 129 + tx];
        float wv1 = Ws[k * 129 + tx + 32];
        float wv2 = Ws[k * 129 + tx + 64];
        float wv3 = Ws[k * 129 + tx + 96];
        #pragma unroll
        for (int r = 0; r < 8; r++) {
            float xv = xs[(ty * 8 + r) * 128 + k];
            acc[r][0] += xv * wv0;
            acc[r][1] += xv * wv1;
            acc[r][2] += xv * wv2;
            acc[r][3] += xv * wv3;
        }
    }

    #pragma unroll
    for (int r = 0; r < 8; r++) {
        size_t R = base + ty * 8 + r;
        #pragma unroll
        for (int cc = 0; cc < 4; cc++) {
            int c = cc * 32 + tx;
            out[R * D + c] = pair[R * D + c] + acc[r][cc] + bo[c];
        }
    }
}

// ================= launch =================
extern "C" void kernel_launch(void* const* d_in, const int* in_sizes, int n_in,
                              void* d_out, int out_size) {
    const float* pair  = (const float*)d_in[0];
    const float* nw    = (const float*)d_in[1];
    const float* nb    = (const float*)d_in[2];
    const float* Wq    = (const float*)d_in[3];
    const float* Wk    = (const float*)d_in[4];
    const float* Wv    = (const float*)d_in[5];
    const float* Wg    = (const float*)d_in[6];
    const float* bg    = (const float*)d_in[7];
    const float* Wo    = (const float*)d_in[8];
    const float* bo    = (const float*)d_in[9];
    const float* Wb    = (const float*)d_in[10];
    float* out = (float*)d_out;

    static bool attr_set = false;
    if (!attr_set) {
        cudaFuncSetAttribute(k_attn, cudaFuncAttributeMaxDynamicSharedMemorySize,
                             SM3_FLOATS * sizeof(float));
        attr_set = true;
    }

    k_ln_bias<<<NROW, 128>>>(pair, nw, nb, Wb);
    k_proj   <<<NROW / 64, 256>>>(Wq, Wk, Wv, Wg, bg);
    k_attn   <<<L * H, 256, SM3_FLOATS * sizeof(float)>>>();
    k_out    <<<NROW / 64, 256>>>(Wo, bo, pair, out);
}

// round 3
// speedup vs baseline: 1.0353x; 1.0353x over previous
#include <cuda_runtime.h>
#include <cstdint>

#define L       320
#define D       128
#define H       4
#define DH      32
#define NROW    (L*L)          // 102400
#define SCALE   0.17677669529663687f   // 1/sqrt(32)
#define LOG2E   1.4426950408889634f

// ---------------- scratch (static device memory, no allocation) ----------------
__device__ float g_x   [NROW * D];   // layernormed pair
__device__ float g_q   [NROW * D];   // [i][h][j][d]  (pre-scaled by SCALE*LOG2E)
__device__ float g_k   [NROW * D];   // [i][h][j][d]
__device__ float g_v   [NROW * D];   // [i][h][j][d]
__device__ float g_g   [NROW * D];   // row layout, sigmoid applied
__device__ float g_o   [NROW * D];   // gated attention output, row layout
__device__ float g_bias[L * H * L];  // [i][h][j]  (pre-scaled by LOG2E)

// ---------------- f32x2 / shared-mem helpers ----------------
__device__ __forceinline__ uint64_t pk2(float lo, float hi) {
    uint64_t r; asm("mov.b64 %0, {%1, %2};" : "=l"(r) : "f"(lo), "f"(hi)); return r;
}
__device__ __forceinline__ float2 up2(uint64_t v) {
    float2 r; asm("mov.b64 {%0, %1}, %2;" : "=f"(r.x), "=f"(r.y) : "l"(v)); return r;
}
__device__ __forceinline__ void fma2(uint64_t& d, uint64_t a, uint64_t b) {
    asm("fma.rn.f32x2 %0, %1, %2, %0;" : "+l"(d) : "l"(a), "l"(b));
}
__device__ __forceinline__ uint64_t lds64(const float* p) {
    uint64_t r; uint32_t a = (uint32_t)__cvta_generic_to_shared(p);
    asm("ld.shared.b64 %0, [%1];" : "=l"(r) : "r"(a)); return r;
}
__device__ __forceinline__ float ex2f(float x) {
    float r; asm("ex2.approx.f32 %0, %1;" : "=f"(r) : "f"(x)); return r;
}

// ================= kernel 1: layernorm + bias projection =================
__global__ void k_ln_bias(const float* __restrict__ pair,
                          const float* __restrict__ nw,
                          const float* __restrict__ nb,
                          const float* __restrict__ Wb) {
    int row = blockIdx.x;
    int t   = threadIdx.x;
    int w   = t >> 5, lane = t & 31;

    float p = pair[(size_t)row * D + t];

    __shared__ float px[D];
    __shared__ float rs[4], rs2[4];
    px[t] = p;

    float s = p, s2 = p * p;
    #pragma unroll
    for (int o = 16; o > 0; o >>= 1) {
        s  += __shfl_xor_sync(0xffffffffu, s,  o);
        s2 += __shfl_xor_sync(0xffffffffu, s2, o);
    }
    if (lane == 0) { rs[w] = s; rs2[w] = s2; }
    __syncthreads();

    float mean = (rs[0] + rs[1] + rs[2] + rs[3]) * (1.0f / 128.0f);
    float var  = (rs2[0] + rs2[1] + rs2[2] + rs2[3]) * (1.0f / 128.0f) - mean * mean;
    float inv  = rsqrtf(var + 1e-5f);
    g_x[(size_t)row * D + t] = (p - mean) * inv * nw[t] + nb[t];

    const float* wb = Wb + w * D;
    float bv = px[lane]      * wb[lane]
             + px[lane + 32] * wb[lane + 32]
             + px[lane + 64] * wb[lane + 64]
             + px[lane + 96] * wb[lane + 96];
    #pragma unroll
    for (int o = 16; o > 0; o >>= 1)
        bv += __shfl_xor_sync(0xffffffffu, bv, o);
    if (lane == 0) {
        int i = row / L, j = row % L;
        g_bias[(i * H + w) * L + j] = bv * LOG2E;
    }
}

// ================= kernel 2: Q/K/V/G projections (FFMA2) =================
__global__ __launch_bounds__(256) void k_proj(const float* __restrict__ Wq,
                                              const float* __restrict__ Wk,
                                              const float* __restrict__ Wv,
                                              const float* __restrict__ Wg,
                                              const float* __restrict__ bg) {
    __shared__ float2 xs2[32 * 128];   // row-pairs of x:  xs2[rp*128+k] = (x[2rp][k], x[2rp+1][k])
    __shared__ float  Ws [128 * 129];  // W transposed: Ws[k*129 + c]
    int t = threadIdx.x;
    int base = blockIdx.x * 64;

    for (int idx = t; idx < 32 * 128; idx += 256) {
        int rp = idx >> 7, k = idx & 127;
        xs2[idx] = make_float2(g_x[(size_t)(base + 2 * rp)     * 128 + k],
                               g_x[(size_t)(base + 2 * rp + 1) * 128 + k]);
    }

    int ty = t >> 5, tx = t & 31;

    for (int m = 0; m < 4; m++) {
        const float* W = (m == 0) ? Wq : (m == 1) ? Wk : (m == 2) ? Wv : Wg;
        __syncthreads();
        for (int idx = t; idx < 128 * 128; idx += 256) {
            int c = idx >> 7, k = idx & 127;
            Ws[k * 129 + c] = W[idx];
        }
        __syncthreads();

        uint64_t acc[4][4];
        #pragma unroll
        for (int rp = 0; rp < 4; rp++)
            #pragma unroll
            for (int cc = 0; cc < 4; cc++) acc[rp][cc] = 0ull;

        #pragma unroll 4
        for (int k = 0; k < 128; k++) {
            float w0 = Ws[k * 129 + tx];
            float w1 = Ws[k * 129 + tx + 32];
            float w2 = Ws[k * 129 + tx + 64];
            float w3 = Ws[k * 129 + tx + 96];
            uint64_t b0 = pk2(w0, w0), b1 = pk2(w1, w1);
            uint64_t b2 = pk2(w2, w2), b3 = pk2(w3, w3);
            #pragma unroll
            for (int rp = 0; rp < 4; rp++) {
                uint64_t a = lds64((const float*)&xs2[(ty * 4 + rp) * 128 + k]);
                fma2(acc[rp][0], a, b0);
                fma2(acc[rp][1], a, b1);
                fma2(acc[rp][2], a, b2);
                fma2(acc[rp][3], a, b3);
            }
        }

        #pragma unroll
        for (int rp = 0; rp < 4; rp++) {
            int R0 = base + ty * 8 + rp * 2;
            int R1 = R0 + 1;
            int i0 = R0 / L, j0 = R0 % L;
            int i1 = R1 / L, j1 = R1 % L;
            if (m < 3) {
                float* dst = (m == 0) ? g_q : (m == 1) ? g_k : g_v;
                float sc = (m == 0) ? (SCALE * LOG2E) : 1.0f;
                #pragma unroll
                for (int cc = 0; cc < 4; cc++) {
                    float2 u = up2(acc[rp][cc]);
                    dst[(((size_t)i0 * H + cc) * L + j0) * DH + tx] = u.x * sc;
                    dst[(((size_t)i1 * H + cc) * L + j1) * DH + tx] = u.y * sc;
                }
            } else {
                #pragma unroll
                for (int cc = 0; cc < 4; cc++) {
                    int c = cc * 32 + tx;
                    float2 u = up2(acc[rp][cc]);
                    float a0 = u.x + bg[c], a1 = u.y + bg[c];
                    g_g[(size_t)R0 * D + c] = 1.0f / (1.0f + __expf(-a0));
                    g_g[(size_t)R1 * D + c] = 1.0f / (1.0f + __expf(-a1));
                }
            }
        }
    }
}

// ================= kernel 3: attention per (row i, head h) =================
// 256 threads, 8 warps; each warp owns 40 query rows, swept 4 at a time.
#define KS_OFF 0                       // 320*33 = 10560
#define VS_OFF 10560                   // 320*32 = 10240 (16B-atom xor swizzle)
#define BS_OFF 20800                   // 320
#define QW_OFF 21120                   // 8 warps * 64 float2 = 1024 floats
#define PW_OFF 22144                   // 8 warps * 640 float2 = 10240 floats
#define SM_FLOATS 32384                // *4 = 129536 bytes

__device__ __forceinline__ float sm_row(float (&v)[10]) {
    float m = v[0];
    #pragma unroll
    for (int jj = 1; jj < 10; jj++) m = fmaxf(m, v[jj]);
    #pragma unroll
    for (int o = 16; o > 0; o >>= 1)
        m = fmaxf(m, __shfl_xor_sync(0xffffffffu, m, o));
    float s = 0.0f;
    #pragma unroll
    for (int jj = 0; jj < 10; jj++) { v[jj] = ex2f(v[jj] - m); s += v[jj]; }
    #pragma unroll
    for (int o = 16; o > 0; o >>= 1)
        s += __shfl_xor_sync(0xffffffffu, s, o);
    return s;
}

__global__ __launch_bounds__(256) void k_attn() {
    extern __shared__ float sm[];
    float* Ks = sm + KS_OFF;
    float* Vs = sm + VS_OFF;
    float* Bs = sm + BS_OFF;

    int blk = blockIdx.x;
    int i = blk >> 2, h = blk & 3;
    int t = threadIdx.x, w = t >> 5, lane = t & 31;

    const float* Kg = g_k + ((size_t)i * H + h) * L * DH;
    const float* Vg = g_v + ((size_t)i * H + h) * L * DH;
    const float* Qg = g_q + ((size_t)i * H + h) * L * DH;

    for (int idx = t; idx < L * DH; idx += 256) {
        int j = idx >> 5, d = idx & 31;
        Ks[j * 33 + d] = Kg[idx];
        Vs[j * 32 + ((((d >> 2) ^ (j & 7)) << 2) | (d & 3))] = Vg[idx];
    }
    for (int idx = t; idx < L; idx += 256)
        Bs[idx] = g_bias[(i * H + h) * L + idx];
    __syncthreads();

    float2* Qw2 = (float2*)(sm + QW_OFF) + w * 64;    // [rp*32 + d]
    float2* Pw2 = (float2*)(sm + PW_OFF) + w * 640;   // [rp*320 + j]
    int jo = lane >> 3, g = lane & 7;

    for (int s = 0; s < 10; s++) {
        int q0 = w * 40 + s * 4;

        // stage q (row-paired)
        Qw2[lane]      = make_float2(Qg[(q0 + 0) * DH + lane], Qg[(q0 + 1) * DH + lane]);
        Qw2[32 + lane] = make_float2(Qg[(q0 + 2) * DH + lane], Qg[(q0 + 3) * DH + lane]);
        __syncwarp();

        // ---- scores: lane owns j = jj*32+lane, 4 rows packed as 2 f32x2 accs ----
        uint64_t a01[10], a23[10];
        #pragma unroll
        for (int jj = 0; jj < 10; jj++) { a01[jj] = 0ull; a23[jj] = 0ull; }

        #pragma unroll 4
        for (int d = 0; d < 32; d++) {
            uint64_t q01 = lds64((const float*)&Qw2[d]);
            uint64_t q23 = lds64((const float*)&Qw2[32 + d]);
            #pragma unroll
            for (int jj = 0; jj < 10; jj++) {
                float kv = Ks[(jj * 32 + lane) * 33 + d];
                uint64_t kk = pk2(kv, kv);
                fma2(a01[jj], q01, kk);
                fma2(a23[jj], q23, kk);
            }
        }

        // ---- softmax (scores already in log2 domain) ----
        float v0[10], v1[10], v2[10], v3[10];
        #pragma unroll
        for (int jj = 0; jj < 10; jj++) {
            float bv = Bs[jj * 32 + lane];
            float2 u = up2(a01[jj]); v0[jj] = u.x + bv; v1[jj] = u.y + bv;
            u = up2(a23[jj]);        v2[jj] = u.x + bv; v3[jj] = u.y + bv;
        }
        float s0 = sm_row(v0), s1 = sm_row(v1), s2 = sm_row(v2), s3 = sm_row(v3);

        #pragma unroll
        for (int jj = 0; jj < 10; jj++) {
            Pw2[jj * 32 + lane]       = make_float2(v0[jj], v1[jj]);
            Pw2[320 + jj * 32 + lane] = make_float2(v2[jj], v3[jj]);
        }
        __syncwarp();

        // ---- PV: lane owns d-quad g, j-offset jo; wide V reads, multicast P reads ----
        uint64_t o01[4], o23[4];
        #pragma unroll
        for (int m = 0; m < 4; m++) { o01[m] = 0ull; o23[m] = 0ull; }

        #pragma unroll 4
        for (int j4 = 0; j4 < 80; j4++) {
            int j = j4 * 4 + jo;
            const float4 vv = *(const float4*)&Vs[j * 32 + ((g ^ (j & 7)) << 2)];
            uint64_t p01 = lds64((const float*)&Pw2[j]);
            uint64_t p23 = lds64((const float*)&Pw2[320 + j]);
            uint64_t b0 = pk2(vv.x, vv.x), b1 = pk2(vv.y, vv.y);
            uint64_t b2 = pk2(vv.z, vv.z), b3 = pk2(vv.w, vv.w);
            fma2(o01[0], p01, b0); fma2(o01[1], p01, b1);
            fma2(o01[2], p01, b2); fma2(o01[3], p01, b3);
            fma2(o23[0], p23, b0); fma2(o23[1], p23, b1);
            fma2(o23[2], p23, b2); fma2(o23[3], p23, b3);
        }

        // reduce partial sums across the 4 jo-lanes sharing a d-quad
        float2 r01[4], r23[4];
        #pragma unroll
        for (int m = 0; m < 4; m++) {
            float2 u = up2(o01[m]);
            u.x += __shfl_xor_sync(0xffffffffu, u.x, 8);
            u.y += __shfl_xor_sync(0xffffffffu, u.y, 8);
            u.x += __shfl_xor_sync(0xffffffffu, u.x, 16);
            u.y += __shfl_xor_sync(0xffffffffu, u.y, 16);
            r01[m] = u;
            u = up2(o23[m]);
            u.x += __shfl_xor_sync(0xffffffffu, u.x, 8);
            u.y += __shfl_xor_sync(0xffffffffu, u.y, 8);
            u.x += __shfl_xor_sync(0xffffffffu, u.x, 16);
            u.y += __shfl_xor_sync(0xffffffffu, u.y, 16);
            r23[m] = u;
        }

        if (jo == 0) {
            float i0 = __fdividef(1.0f, s0), i1 = __fdividef(1.0f, s1);
            float i2 = __fdividef(1.0f, s2), i3 = __fdividef(1.0f, s3);
            size_t R = ((size_t)i * L + q0) * D + h * DH + g * 4;
            float4 g4;
            g4 = *(const float4*)&g_g[R];
            *(float4*)&g_o[R] = make_float4(r01[0].x * i0 * g4.x, r01[1].x * i0 * g4.y,
                                            r01[2].x * i0 * g4.z, r01[3].x * i0 * g4.w);
            g4 = *(const float4*)&g_g[R + D];
            *(float4*)&g_o[R + D] = make_float4(r01[0].y * i1 * g4.x, r01[1].y * i1 * g4.y,
                                                r01[2].y * i1 * g4.z, r01[3].y * i1 * g4.w);
            g4 = *(const float4*)&g_g[R + 2 * D];
            *(float4*)&g_o[R + 2 * D] = make_float4(r23[0].x * i2 * g4.x, r23[1].x * i2 * g4.y,
                                                    r23[2].x * i2 * g4.z, r23[3].x * i2 * g4.w);
            g4 = *(const float4*)&g_g[R + 3 * D];
            *(float4*)&g_o[R + 3 * D] = make_float4(r23[0].y * i3 * g4.x, r23[1].y * i3 * g4.y,
                                                    r23[2].y * i3 * g4.z, r23[3].y * i3 * g4.w);
        }
        __syncwarp();
    }
}

// ================= kernel 4: output projection + residual (FFMA2) =================
__global__ __launch_bounds__(256) void k_out(const float* __restrict__ Wo,
                                             const float* __restrict__ bo,
                                             const float* __restrict__ pair,
                                             float* __restrict__ out) {
    __shared__ float2 xs2[32 * 128];
    __shared__ float  Ws [128 * 129];
    int t = threadIdx.x;
    int base = blockIdx.x * 64;

    for (int idx = t; idx < 32 * 128; idx += 256) {
        int rp = idx >> 7, k = idx & 127;
        xs2[idx] = make_float2(g_o[(size_t)(base + 2 * rp)     * 128 + k],
                               g_o[(size_t)(base + 2 * rp + 1) * 128 + k]);
    }
    for (int idx = t; idx < 128 * 128; idx += 256) {
        int c = idx >> 7, k = idx & 127;
        Ws[k * 129 + c] = Wo[idx];
    }
    __syncthreads();

    int ty = t >> 5, tx = t & 31;
    uint64_t acc[4][4];
    #pragma unroll
    for (int rp = 0; rp < 4; rp++)
        #pragma unroll
        for (int cc = 0; cc < 4; cc++) acc[rp][cc] = 0ull;

    #pragma unroll 4
    for (int k = 0; k < 128; k++) {
        float w0 = Ws[k * 129 + tx];
        float w1 = Ws[k * 129 + tx + 32];
        float w2 = Ws[k * 129 + tx + 64];
        float w3 = Ws[k * 129 + tx + 96];
        uint64_t b0 = pk2(w0, w0), b1 = pk2(w1, w1);
        uint64_t b2 = pk2(w2, w2), b3 = pk2(w3, w3);
        #pragma unroll
        for (int rp = 0; rp < 4; rp++) {
            uint64_t a = lds64((const float*)&xs2[(ty * 4 + rp) * 128 + k]);
            fma2(acc[rp][0], a, b0);
            fma2(acc[rp][1], a, b1);
            fma2(acc[rp][2], a, b2);
            fma2(acc[rp][3], a, b3);
        }
    }

    #pragma unroll
    for (int rp = 0; rp < 4; rp++) {
        size_t R0 = base + ty * 8 + rp * 2;
        size_t R1 = R0 + 1;
        #pragma unroll
        for (int cc = 0; cc < 4; cc++) {
            int c = cc * 32 + tx;
            float2 u = up2(acc[rp][cc]);
            out[R0 * D + c] = pair[R0 * D + c] + u.x + bo[c];
            out[R1 * D + c] = pair[R1 * D + c] + u.y + bo[c];
        }
    }
}

// ================= launch =================
extern "C" void kernel_launch(void* const* d_in, const int* in_sizes, int n_in,
                              void* d_out, int out_size) {
    const float* pair  = (const float*)d_in[0];
    const float* nw    = (const float*)d_in[1];
    const float* nb    = (const float*)d_in[2];
    const float* Wq    = (const float*)d_in[3];
    const float* Wk    = (const float*)d_in[4];
    const float* Wv    = (const float*)d_in[5];
    const float* Wg    = (const float*)d_in[6];
    const float* bg    = (const float*)d_in[7];
    const float* Wo    = (const float*)d_in[8];
    const float* bo    = (const float*)d_in[9];
    const float* Wb    = (const float*)d_in[10];
    float* out = (float*)d_out;

    static bool attr_set = false;
    if (!attr_set) {
        cudaFuncSetAttribute(k_attn, cudaFuncAttributeMaxDynamicSharedMemorySize,
                             SM_FLOATS * sizeof(float));
        attr_set = true;
    }

    k_ln_bias<<<NROW, 128>>>(pair, nw, nb, Wb);
    k_proj   <<<NROW / 64, 256>>>(Wq, Wk, Wv, Wg, bg);
    k_attn   <<<L * H, 256, SM_FLOATS * sizeof(float)>>>();
    k_out    <<<NROW / 64, 256>>>(Wo, bo, pair, out);
}

// round 7
// speedup vs baseline: 1.1577x; 1.1182x over previous
#include <cuda_runtime.h>
#include <cuda_bf16.h>
#include <cstdint>

#define L       320
#define D       128
#define H       4
#define DH      32
#define NROW    (L*L)          // 102400
#define SCALE   0.17677669529663687f   // 1/sqrt(32)
#define LOG2E   1.4426950408889634f

// ---------------- scratch (static device memory, no allocation) ----------------
__device__ float g_x   [NROW * D];   // layernormed pair
__device__ float g_q   [NROW * D];   // [i][h][j][d]  (pre-scaled by SCALE*LOG2E)
__device__ float g_k   [NROW * D];
__device__ float g_v   [NROW * D];
__device__ float g_g   [NROW * D];   // row layout, sigmoid applied
__device__ float g_o   [NROW * D];   // gated attention output, row layout
__device__ float g_bias[L * H * L];  // [i][h][j]  (pre-scaled by LOG2E)

// single extern shared symbol for all kernels
extern __shared__ char smx[];

// ---------------- helpers ----------------
__device__ __forceinline__ uint64_t pk2(float lo, float hi) {
    uint64_t r; asm("mov.b64 %0, {%1, %2};" : "=l"(r) : "f"(lo), "f"(hi)); return r;
}
__device__ __forceinline__ float2 up2(uint64_t v) {
    float2 r; asm("mov.b64 {%0, %1}, %2;" : "=f"(r.x), "=f"(r.y) : "l"(v)); return r;
}
__device__ __forceinline__ void fma2(uint64_t& d, uint64_t a, uint64_t b) {
    asm("fma.rn.f32x2 %0, %1, %2, %0;" : "+l"(d) : "l"(a), "l"(b));
}
__device__ __forceinline__ uint64_t lds64(const float* p) {
    uint64_t r; uint32_t a = (uint32_t)__cvta_generic_to_shared(p);
    asm("ld.shared.b64 %0, [%1];" : "=l"(r) : "r"(a)); return r;
}
__device__ __forceinline__ float ex2f(float x) {
    float r; asm("ex2.approx.f32 %0, %1;" : "=f"(r) : "f"(x)); return r;
}
__device__ __forceinline__ uint32_t smem_u32(const void* p) {
    return (uint32_t)__cvta_generic_to_shared(p);
}
__device__ __forceinline__ void ldsm4(uint32_t* r, uint32_t addr) {
    asm volatile("ldmatrix.sync.aligned.m8n8.x4.shared.b16 {%0,%1,%2,%3}, [%4];"
                 : "=r"(r[0]), "=r"(r[1]), "=r"(r[2]), "=r"(r[3]) : "r"(addr));
}
__device__ __forceinline__ void mma16816(float* c, const uint32_t* a, const uint32_t* b) {
    asm volatile("mma.sync.aligned.m16n8k16.row.col.f32.bf16.bf16.f32 "
                 "{%0,%1,%2,%3}, {%4,%5,%6,%7}, {%8,%9}, {%0,%1,%2,%3};"
                 : "+f"(c[0]), "+f"(c[1]), "+f"(c[2]), "+f"(c[3])
                 : "r"(a[0]), "r"(a[1]), "r"(a[2]), "r"(a[3]), "r"(b[0]), "r"(b[1]));
}
// split fp32 pair -> (hi bf16x2, lo bf16x2) packed as uint32
__device__ __forceinline__ void split2(float x0, float x1, uint32_t& hi, uint32_t& lo) {
    __nv_bfloat16 h0 = __float2bfloat16(x0);
    __nv_bfloat16 h1 = __float2bfloat16(x1);
    __nv_bfloat16 l0 = __float2bfloat16(x0 - __bfloat162float(h0));
    __nv_bfloat16 l1 = __float2bfloat16(x1 - __bfloat162float(h1));
    __nv_bfloat162 hp = {h0, h1}, lp = {l0, l1};
    hi = *(uint32_t*)&hp; lo = *(uint32_t*)&lp;
}

// shared tile geometry: 128 rows x 136 bf16 (272B row stride, conflict-free ldmatrix)
#define TROW   272
#define TBYTES (128 * TROW)      // 34816
#define XH_OFF 0
#define XL_OFF TBYTES
#define WH_OFF (2 * TBYTES)
#define WL_OFF (3 * TBYTES)
#define GEMM_SMEM (4 * TBYTES)   // 139264

// ================= kernel 1: layernorm + bias projection =================
__global__ void k_ln_bias(const float* __restrict__ pair,
                          const float* __restrict__ nw,
                          const float* __restrict__ nb,
                          const float* __restrict__ Wb) {
    int row = blockIdx.x;
    int t   = threadIdx.x;
    int w   = t >> 5, lane = t & 31;

    float p = pair[(size_t)row * D + t];

    __shared__ float px[D];
    __shared__ float rs[4], rs2[4];
    px[t] = p;

    float s = p, s2 = p * p;
    #pragma unroll
    for (int o = 16; o > 0; o >>= 1) {
        s  += __shfl_xor_sync(0xffffffffu, s,  o);
        s2 += __shfl_xor_sync(0xffffffffu, s2, o);
    }
    if (lane == 0) { rs[w] = s; rs2[w] = s2; }
    __syncthreads();

    float mean = (rs[0] + rs[1] + rs[2] + rs[3]) * (1.0f / 128.0f);
    float var  = (rs2[0] + rs2[1] + rs2[2] + rs2[3]) * (1.0f / 128.0f) - mean * mean;
    float inv  = rsqrtf(var + 1e-5f);
    g_x[(size_t)row * D + t] = (p - mean) * inv * nw[t] + nb[t];

    const float* wb = Wb + w * D;
    float bv = px[lane]      * wb[lane]
             + px[lane + 32] * wb[lane + 32]
             + px[lane + 64] * wb[lane + 64]
             + px[lane + 96] * wb[lane + 96];
    #pragma unroll
    for (int o = 16; o > 0; o >>= 1)
        bv += __shfl_xor_sync(0xffffffffu, bv, o);
    if (lane == 0) {
        int i = row / L, j = row % L;
        g_bias[(i * H + w) * L + j] = bv * LOG2E;
    }
}

// ---------- shared staging: fp32 [rows x 128] -> bf16 hi/lo tiles ----------
__device__ __forceinline__ void stage_tile(const float* __restrict__ src, char* sm,
                                           int hi_off, int lo_off, int t) {
    for (int idx = t; idx < 128 * 64; idx += 256) {
        int r = idx >> 6, cp = idx & 63;
        float2 v = *(const float2*)&src[(size_t)r * 128 + cp * 2];
        uint32_t hi, lo;
        split2(v.x, v.y, hi, lo);
        *(uint32_t*)(sm + hi_off + r * TROW + cp * 4) = hi;
        *(uint32_t*)(sm + lo_off + r * TROW + cp * 4) = lo;
    }
}

// ---------- 3-term bf16-split 128x128x128 GEMM into registers ----------
// warp tile: 64m x 32n; acc[mt][nt][4]
__device__ __forceinline__ void gemm_tile(uint32_t sb, float (&acc)[4][4][4],
                                          int lane, int wm, int wn) {
    int gq = lane >> 3, r8 = lane & 7;
    uint32_t a_off = (uint32_t)(wm * 64 + (gq & 1) * 8 + r8) * TROW + (uint32_t)(gq >> 1) * 16;
    uint32_t b_off = (uint32_t)(wn * 32 + (gq >> 1) * 8 + r8) * TROW + (uint32_t)(gq & 1) * 16;

    #pragma unroll
    for (int term = 0; term < 3; term++) {
        uint32_t abase = sb + ((term == 2) ? XL_OFF : XH_OFF) + a_off;
        uint32_t bbase = sb + ((term == 1) ? WL_OFF : WH_OFF) + b_off;
        #pragma unroll
        for (int ks = 0; ks < 8; ks++) {
            uint32_t kb = ks * 32;
            uint32_t a[4][4], b[2][4];
            #pragma unroll
            for (int mt = 0; mt < 4; mt++)
                ldsm4(a[mt], abase + mt * (16 * TROW) + kb);
            #pragma unroll
            for (int nb = 0; nb < 2; nb++)
                ldsm4(b[nb], bbase + nb * (16 * TROW) + kb);
            #pragma unroll
            for (int mt = 0; mt < 4; mt++) {
                mma16816(acc[mt][0], a[mt], &b[0][0]);
                mma16816(acc[mt][1], a[mt], &b[0][2]);
                mma16816(acc[mt][2], a[mt], &b[1][0]);
                mma16816(acc[mt][3], a[mt], &b[1][2]);
            }
        }
    }
}

// ================= kernel 2: Q/K/V/G projections via mma.sync =================
__global__ __launch_bounds__(256) void k_proj(const float* __restrict__ Wq,
                                              const float* __restrict__ Wk,
                                              const float* __restrict__ Wv,
                                              const float* __restrict__ Wg,
                                              const float* __restrict__ bg) {
    char* sm = smx;
    uint32_t sb = smem_u32(sm);
    int t = threadIdx.x, w = t >> 5, lane = t & 31;
    int wm = w & 1, wn = w >> 1;
    int base = blockIdx.x * 128;

    stage_tile(g_x + (size_t)base * 128, sm, XH_OFF, XL_OFF, t);

    for (int m = 0; m < 4; m++) {
        const float* W = (m == 0) ? Wq : (m == 1) ? Wk : (m == 2) ? Wv : Wg;
        __syncthreads();   // previous mma reads done / X staged
        stage_tile(W, sm, WH_OFF, WL_OFF, t);
        __syncthreads();

        float acc[4][4][4];
        #pragma unroll
        for (int mt = 0; mt < 4; mt++)
            #pragma unroll
            for (int nt = 0; nt < 4; nt++)
                #pragma unroll
                for (int k = 0; k < 4; k++) acc[mt][nt][k] = 0.0f;

        gemm_tile(sb, acc, lane, wm, wn);

        // epilogue: registers -> global
        #pragma unroll
        for (int mt = 0; mt < 4; mt++) {
            #pragma unroll
            for (int nt = 0; nt < 4; nt++) {
                int col = wn * 32 + nt * 8 + (lane & 3) * 2;
                #pragma unroll
                for (int half = 0; half < 2; half++) {
                    int R = base + wm * 64 + mt * 16 + (lane >> 2) + half * 8;
                    float v0 = acc[mt][nt][half * 2];
                    float v1 = acc[mt][nt][half * 2 + 1];
                    int i = R / L, j = R % L;
                    if (m < 3) {
                        float* dst = (m == 0) ? g_q : (m == 1) ? g_k : g_v;
                        float sc = (m == 0) ? (SCALE * LOG2E) : 1.0f;
                        int h = col >> 5, d = col & 31;
                        *(float2*)&dst[(((size_t)i * H + h) * L + j) * DH + d] =
                            make_float2(v0 * sc, v1 * sc);
                    } else {
                        float a0 = v0 + bg[col], a1 = v1 + bg[col + 1];
                        *(float2*)&g_g[(size_t)R * D + col] =
                            make_float2(1.0f / (1.0f + __expf(-a0)),
                                        1.0f / (1.0f + __expf(-a1)));
                    }
                }
            }
        }
    }
}

// ================= kernel 3: attention per (row i, head h) — unchanged =================
#define KS_OFF 0
#define VS_OFF 10560
#define BS_OFF 20800
#define QW_OFF 21120
#define PW_OFF 22144
#define SM_FLOATS 32384

__device__ __forceinline__ float sm_row(float (&v)[10]) {
    float m = v[0];
    #pragma unroll
    for (int jj = 1; jj < 10; jj++) m = fmaxf(m, v[jj]);
    #pragma unroll
    for (int o = 16; o > 0; o >>= 1)
        m = fmaxf(m, __shfl_xor_sync(0xffffffffu, m, o));
    float s = 0.0f;
    #pragma unroll
    for (int jj = 0; jj < 10; jj++) { v[jj] = ex2f(v[jj] - m); s += v[jj]; }
    #pragma unroll
    for (int o = 16; o > 0; o >>= 1)
        s += __shfl_xor_sync(0xffffffffu, s, o);
    return s;
}

__global__ __launch_bounds__(256) void k_attn() {
    float* sm = (float*)smx;
    float* Ks = sm + KS_OFF;
    float* Vs = sm + VS_OFF;
    float* Bs = sm + BS_OFF;

    int blk = blockIdx.x;
    int i = blk >> 2, h = blk & 3;
    int t = threadIdx.x, w = t >> 5, lane = t & 31;

    const float* Kg = g_k + ((size_t)i * H + h) * L * DH;
    const float* Vg = g_v + ((size_t)i * H + h) * L * DH;
    const float* Qg = g_q + ((size_t)i * H + h) * L * DH;

    for (int idx = t; idx < L * DH; idx += 256) {
        int j = idx >> 5, d = idx & 31;
        Ks[j * 33 + d] = Kg[idx];
        Vs[j * 32 + ((((d >> 2) ^ (j & 7)) << 2) | (d & 3))] = Vg[idx];
    }
    for (int idx = t; idx < L; idx += 256)
        Bs[idx] = g_bias[(i * H + h) * L + idx];
    __syncthreads();

    float2* Qw2 = (float2*)(sm + QW_OFF) + w * 64;
    float2* Pw2 = (float2*)(sm + PW_OFF) + w * 640;
    int jo = lane >> 3, g = lane & 7;

    for (int s = 0; s < 10; s++) {
        int q0 = w * 40 + s * 4;

        Qw2[lane]      = make_float2(Qg[(q0 + 0) * DH + lane], Qg[(q0 + 1) * DH + lane]);
        Qw2[32 + lane] = make_float2(Qg[(q0 + 2) * DH + lane], Qg[(q0 + 3) * DH + lane]);
        __syncwarp();

        uint64_t a01[10], a23[10];
        #pragma unroll
        for (int jj = 0; jj < 10; jj++) { a01[jj] = 0ull; a23[jj] = 0ull; }

        #pragma unroll 4
        for (int d = 0; d < 32; d++) {
            uint64_t q01 = lds64((const float*)&Qw2[d]);
            uint64_t q23 = lds64((const float*)&Qw2[32 + d]);
            #pragma unroll
            for (int jj = 0; jj < 10; jj++) {
                float kv = Ks[(jj * 32 + lane) * 33 + d];
                uint64_t kk = pk2(kv, kv);
                fma2(a01[jj], q01, kk);
                fma2(a23[jj], q23, kk);
            }
        }

        float v0[10], v1[10], v2[10], v3[10];
        #pragma unroll
        for (int jj = 0; jj < 10; jj++) {
            float bv = Bs[jj * 32 + lane];
            float2 u = up2(a01[jj]); v0[jj] = u.x + bv; v1[jj] = u.y + bv;
            u = up2(a23[jj]);        v2[jj] = u.x + bv; v3[jj] = u.y + bv;
        }
        float s0 = sm_row(v0), s1 = sm_row(v1), s2 = sm_row(v2), s3 = sm_row(v3);

        #pragma unroll
        for (int jj = 0; jj < 10; jj++) {
            Pw2[jj * 32 + lane]       = make_float2(v0[jj], v1[jj]);
            Pw2[320 + jj * 32 + lane] = make_float2(v2[jj], v3[jj]);
        }
        __syncwarp();

        uint64_t o01[4], o23[4];
        #pragma unroll
        for (int m = 0; m < 4; m++) { o01[m] = 0ull; o23[m] = 0ull; }

        #pragma unroll 4
        for (int j4 = 0; j4 < 80; j4++) {
            int j = j4 * 4 + jo;
            const float4 vv = *(const float4*)&Vs[j * 32 + ((g ^ (j & 7)) << 2)];
            uint64_t p01 = lds64((const float*)&Pw2[j]);
            uint64_t p23 = lds64((const float*)&Pw2[320 + j]);
            uint64_t b0 = pk2(vv.x, vv.x), b1 = pk2(vv.y, vv.y);
            uint64_t b2 = pk2(vv.z, vv.z), b3 = pk2(vv.w, vv.w);
            fma2(o01[0], p01, b0); fma2(o01[1], p01, b1);
            fma2(o01[2], p01, b2); fma2(o01[3], p01, b3);
            fma2(o23[0], p23, b0); fma2(o23[1], p23, b1);
            fma2(o23[2], p23, b2); fma2(o23[3], p23, b3);
        }

        float2 r01[4], r23[4];
        #pragma unroll
        for (int m = 0; m < 4; m++) {
            float2 u = up2(o01[m]);
            u.x += __shfl_xor_sync(0xffffffffu, u.x, 8);
            u.y += __shfl_xor_sync(0xffffffffu, u.y, 8);
            u.x += __shfl_xor_sync(0xffffffffu, u.x, 16);
            u.y += __shfl_xor_sync(0xffffffffu, u.y, 16);
            r01[m] = u;
            u = up2(o23[m]);
            u.x += __shfl_xor_sync(0xffffffffu, u.x, 8);
            u.y += __shfl_xor_sync(0xffffffffu, u.y, 8);
            u.x += __shfl_xor_sync(0xffffffffu, u.x, 16);
            u.y += __shfl_xor_sync(0xffffffffu, u.y, 16);
            r23[m] = u;
        }

        if (jo == 0) {
            float i0 = __fdividef(1.0f, s0), i1 = __fdividef(1.0f, s1);
            float i2 = __fdividef(1.0f, s2), i3 = __fdividef(1.0f, s3);
            size_t R = ((size_t)i * L + q0) * D + h * DH + g * 4;
            float4 g4;
            g4 = *(const float4*)&g_g[R];
            *(float4*)&g_o[R] = make_float4(r01[0].x * i0 * g4.x, r01[1].x * i0 * g4.y,
                                            r01[2].x * i0 * g4.z, r01[3].x * i0 * g4.w);
            g4 = *(const float4*)&g_g[R + D];
            *(float4*)&g_o[R + D] = make_float4(r01[0].y * i1 * g4.x, r01[1].y * i1 * g4.y,
                                                r01[2].y * i1 * g4.z, r01[3].y * i1 * g4.w);
            g4 = *(const float4*)&g_g[R + 2 * D];
            *(float4*)&g_o[R + 2 * D] = make_float4(r23[0].x * i2 * g4.x, r23[1].x * i2 * g4.y,
                                                    r23[2].x * i2 * g4.z, r23[3].x * i2 * g4.w);
            g4 = *(const float4*)&g_g[R + 3 * D];
            *(float4*)&g_o[R + 3 * D] = make_float4(r23[0].y * i3 * g4.x, r23[1].y * i3 * g4.y,
                                                    r23[2].y * i3 * g4.z, r23[3].y * i3 * g4.w);
        }
        __syncwarp();
    }
}

// ================= kernel 4: output projection + residual via mma.sync =================
__global__ __launch_bounds__(256) void k_out(const float* __restrict__ Wo,
                                             const float* __restrict__ bo,
                                             const float* __restrict__ pair,
                                             float* __restrict__ out) {
    char* sm = smx;
    uint32_t sb = smem_u32(sm);
    int t = threadIdx.x, w = t >> 5, lane = t & 31;
    int wm = w & 1, wn = w >> 1;
    int base = blockIdx.x * 128;

    stage_tile(g_o + (size_t)base * 128, sm, XH_OFF, XL_OFF, t);
    stage_tile(Wo, sm, WH_OFF, WL_OFF, t);
    __syncthreads();

    float acc[4][4][4];
    #pragma unroll
    for (int mt = 0; mt < 4; mt++)
        #pragma unroll
        for (int nt = 0; nt < 4; nt++)
            #pragma unroll
            for (int k = 0; k < 4; k++) acc[mt][nt][k] = 0.0f;

    gemm_tile(sb, acc, lane, wm, wn);

    #pragma unroll
    for (int mt = 0; mt < 4; mt++) {
        #pragma unroll
        for (int nt = 0; nt < 4; nt++) {
            int col = wn * 32 + nt * 8 + (lane & 3) * 2;
            float2 bov = *(const float2*)&bo[col];
            #pragma unroll
            for (int half = 0; half < 2; half++) {
                size_t R = (size_t)base + wm * 64 + mt * 16 + (lane >> 2) + half * 8;
                float2 pv = *(const float2*)&pair[R * D + col];
                *(float2*)&out[R * D + col] =
                    make_float2(pv.x + acc[mt][nt][half * 2]     + bov.x,
                                pv.y + acc[mt][nt][half * 2 + 1] + bov.y);
            }
        }
    }
}

// ================= launch =================
extern "C" void kernel_launch(void* const* d_in, const int* in_sizes, int n_in,
                              void* d_out, int out_size) {
    const float* pair  = (const float*)d_in[0];
    const float* nw    = (const float*)d_in[1];
    const float* nb    = (const float*)d_in[2];
    const float* Wq    = (const float*)d_in[3];
    const float* Wk    = (const float*)d_in[4];
    const float* Wv    = (const float*)d_in[5];
    const float* Wg    = (const float*)d_in[6];
    const float* bg    = (const float*)d_in[7];
    const float* Wo    = (const float*)d_in[8];
    const float* bo    = (const float*)d_in[9];
    const float* Wb    = (const float*)d_in[10];
    float* out = (float*)d_out;

    static bool attr_set = false;
    if (!attr_set) {
        cudaFuncSetAttribute(k_attn, cudaFuncAttributeMaxDynamicSharedMemorySize,
                             SM_FLOATS * sizeof(float));
        cudaFuncSetAttribute(k_proj, cudaFuncAttributeMaxDynamicSharedMemorySize, GEMM_SMEM);
        cudaFuncSetAttribute(k_out,  cudaFuncAttributeMaxDynamicSharedMemorySize, GEMM_SMEM);
        attr_set = true;
    }

    k_ln_bias<<<NROW, 128>>>(pair, nw, nb, Wb);
    k_proj   <<<NROW / 128, 256, GEMM_SMEM>>>(Wq, Wk, Wv, Wg, bg);
    k_attn   <<<L * H, 256, SM_FLOATS * sizeof(float)>>>();
    k_out    <<<NROW / 128, 256, GEMM_SMEM>>>(Wo, bo, pair, out);
}

// round 9
// speedup vs baseline: 1.9363x; 1.6725x over previous
#include <cuda_runtime.h>
#include <cuda_bf16.h>
#include <cuda_fp16.h>
#include <cstdint>

#define L       320
#define D       128
#define H       4
#define DH      32
#define NROW    (L*L)          // 102400
#define SCALE   0.17677669529663687f   // 1/sqrt(32)
#define LOG2E   1.4426950408889634f

// ---------------- scratch (static device memory, no allocation) ----------------
__device__ float g_x   [NROW * D];   // layernormed pair
__device__ float g_q   [NROW * D];   // [i][h][j][d]  (pre-scaled by SCALE*LOG2E)
__device__ float g_k   [NROW * D];
__device__ float g_v   [NROW * D];
__device__ float g_g   [NROW * D];   // row layout, sigmoid applied
__device__ float g_o   [NROW * D];   // gated attention output, row layout
__device__ float g_bias[L * H * L];  // [i][h][j]  (pre-scaled by LOG2E)

// single extern shared symbol for all kernels
extern __shared__ char smx[];

// ---------------- helpers ----------------
__device__ __forceinline__ float ex2f(float x) {
    float r; asm("ex2.approx.f32 %0, %1;" : "=f"(r) : "f"(x)); return r;
}
__device__ __forceinline__ uint32_t smem_u32(const void* p) {
    return (uint32_t)__cvta_generic_to_shared(p);
}
__device__ __forceinline__ void ldsm4(uint32_t* r, uint32_t addr) {
    asm volatile("ldmatrix.sync.aligned.m8n8.x4.shared.b16 {%0,%1,%2,%3}, [%4];"
                 : "=r"(r[0]), "=r"(r[1]), "=r"(r[2]), "=r"(r[3]) : "r"(addr));
}
__device__ __forceinline__ void mma16816(float* c, const uint32_t* a, const uint32_t* b) {
    asm volatile("mma.sync.aligned.m16n8k16.row.col.f32.bf16.bf16.f32 "
                 "{%0,%1,%2,%3}, {%4,%5,%6,%7}, {%8,%9}, {%0,%1,%2,%3};"
                 : "+f"(c[0]), "+f"(c[1]), "+f"(c[2]), "+f"(c[3])
                 : "r"(a[0]), "r"(a[1]), "r"(a[2]), "r"(a[3]), "r"(b[0]), "r"(b[1]));
}
__device__ __forceinline__ void mma16816h(float* c, const uint32_t* a, const uint32_t* b) {
    asm volatile("mma.sync.aligned.m16n8k16.row.col.f32.f16.f16.f32 "
                 "{%0,%1,%2,%3}, {%4,%5,%6,%7}, {%8,%9}, {%0,%1,%2,%3};"
                 : "+f"(c[0]), "+f"(c[1]), "+f"(c[2]), "+f"(c[3])
                 : "r"(a[0]), "r"(a[1]), "r"(a[2]), "r"(a[3]), "r"(b[0]), "r"(b[1]));
}
// split fp32 pair -> (hi bf16x2, lo bf16x2) packed as uint32
__device__ __forceinline__ void split2(float x0, float x1, uint32_t& hi, uint32_t& lo) {
    __nv_bfloat16 h0 = __float2bfloat16(x0);
    __nv_bfloat16 h1 = __float2bfloat16(x1);
    __nv_bfloat16 l0 = __float2bfloat16(x0 - __bfloat162float(h0));
    __nv_bfloat16 l1 = __float2bfloat16(x1 - __bfloat162float(h1));
    __nv_bfloat162 hp = {h0, h1}, lp = {l0, l1};
    hi = *(uint32_t*)&hp; lo = *(uint32_t*)&lp;
}
// fp32 pair -> fp16 hi/lo packed
__device__ __forceinline__ void cvth2(float a, float b, uint32_t& hi, uint32_t& lo) {
    __half ha = __float2half_rn(a), hb = __float2half_rn(b);
    __half la = __float2half_rn(a - __half2float(ha));
    __half lb = __float2half_rn(b - __half2float(hb));
    hi = (uint32_t)__half_as_ushort(ha) | ((uint32_t)__half_as_ushort(hb) << 16);
    lo = (uint32_t)__half_as_ushort(la) | ((uint32_t)__half_as_ushort(lb) << 16);
}

// shared tile geometry for GEMM kernels: 128 x 136 bf16 (272B stride)
#define TROW   272
#define TBYTES (128 * TROW)      // 34816
#define XH_OFF 0
#define XL_OFF TBYTES
#define WH_OFF (2 * TBYTES)
#define WL_OFF (3 * TBYTES)
#define GEMM_SMEM (4 * TBYTES)   // 139264

// ================= kernel 1: layernorm + bias projection =================
__global__ void k_ln_bias(const float* __restrict__ pair,
                          const float* __restrict__ nw,
                          const float* __restrict__ nb,
                          const float* __restrict__ Wb) {
    int row = blockIdx.x;
    int t   = threadIdx.x;
    int w   = t >> 5, lane = t & 31;

    float p = pair[(size_t)row * D + t];

    __shared__ float px[D];
    __shared__ float rs[4], rs2[4];
    px[t] = p;

    float s = p, s2 = p * p;
    #pragma unroll
    for (int o = 16; o > 0; o >>= 1) {
        s  += __shfl_xor_sync(0xffffffffu, s,  o);
        s2 += __shfl_xor_sync(0xffffffffu, s2, o);
    }
    if (lane == 0) { rs[w] = s; rs2[w] = s2; }
    __syncthreads();

    float mean = (rs[0] + rs[1] + rs[2] + rs[3]) * (1.0f / 128.0f);
    float var  = (rs2[0] + rs2[1] + rs2[2] + rs2[3]) * (1.0f / 128.0f) - mean * mean;
    float inv  = rsqrtf(var + 1e-5f);
    g_x[(size_t)row * D + t] = (p - mean) * inv * nw[t] + nb[t];

    const float* wb = Wb + w * D;
    float bv = px[lane]      * wb[lane]
             + px[lane + 32] * wb[lane + 32]
             + px[lane + 64] * wb[lane + 64]
             + px[lane + 96] * wb[lane + 96];
    #pragma unroll
    for (int o = 16; o > 0; o >>= 1)
        bv += __shfl_xor_sync(0xffffffffu, bv, o);
    if (lane == 0) {
        int i = row / L, j = row % L;
        g_bias[(i * H + w) * L + j] = bv * LOG2E;
    }
}

// ---------- shared staging: fp32 [rows x 128] -> bf16 hi/lo tiles ----------
__device__ __forceinline__ void stage_tile(const float* __restrict__ src, char* sm,
                                           int hi_off, int lo_off, int t) {
    for (int idx = t; idx < 128 * 64; idx += 256) {
        int r = idx >> 6, cp = idx & 63;
        float2 v = *(const float2*)&src[(size_t)r * 128 + cp * 2];
        uint32_t hi, lo;
        split2(v.x, v.y, hi, lo);
        *(uint32_t*)(sm + hi_off + r * TROW + cp * 4) = hi;
        *(uint32_t*)(sm + lo_off + r * TROW + cp * 4) = lo;
    }
}

// ---------- 3-term bf16-split 128x128x128 GEMM into registers ----------
__device__ __forceinline__ void gemm_tile(uint32_t sb, float (&acc)[4][4][4],
                                          int lane, int wm, int wn) {
    int gq = lane >> 3, r8 = lane & 7;
    uint32_t a_off = (uint32_t)(wm * 64 + (gq & 1) * 8 + r8) * TROW + (uint32_t)(gq >> 1) * 16;
    uint32_t b_off = (uint32_t)(wn * 32 + (gq >> 1) * 8 + r8) * TROW + (uint32_t)(gq & 1) * 16;

    #pragma unroll
    for (int term = 0; term < 3; term++) {
        uint32_t abase = sb + ((term == 2) ? XL_OFF : XH_OFF) + a_off;
        uint32_t bbase = sb + ((term == 1) ? WL_OFF : WH_OFF) + b_off;
        #pragma unroll
        for (int ks = 0; ks < 8; ks++) {
            uint32_t kb = ks * 32;
            uint32_t a[4][4], b[2][4];
            #pragma unroll
            for (int mt = 0; mt < 4; mt++)
                ldsm4(a[mt], abase + mt * (16 * TROW) + kb);
            #pragma unroll
            for (int nb = 0; nb < 2; nb++)
                ldsm4(b[nb], bbase + nb * (16 * TROW) + kb);
            #pragma unroll
            for (int mt = 0; mt < 4; mt++) {
                mma16816(acc[mt][0], a[mt], &b[0][0]);
                mma16816(acc[mt][1], a[mt], &b[0][2]);
                mma16816(acc[mt][2], a[mt], &b[1][0]);
                mma16816(acc[mt][3], a[mt], &b[1][2]);
            }
        }
    }
}

// ================= kernel 2: Q/K/V/G projections via mma.sync =================
__global__ __launch_bounds__(256) void k_proj(const float* __restrict__ Wq,
                                              const float* __restrict__ Wk,
                                              const float* __restrict__ Wv,
                                              const float* __restrict__ Wg,
                                              const float* __restrict__ bg) {
    char* sm = smx;
    uint32_t sb = smem_u32(sm);
    int t = threadIdx.x, w = t >> 5, lane = t & 31;
    int wm = w & 1, wn = w >> 1;
    int base = blockIdx.x * 128;

    stage_tile(g_x + (size_t)base * 128, sm, XH_OFF, XL_OFF, t);

    for (int m = 0; m < 4; m++) {
        const float* W = (m == 0) ? Wq : (m == 1) ? Wk : (m == 2) ? Wv : Wg;
        __syncthreads();
        stage_tile(W, sm, WH_OFF, WL_OFF, t);
        __syncthreads();

        float acc[4][4][4];
        #pragma unroll
        for (int mt = 0; mt < 4; mt++)
            #pragma unroll
            for (int nt = 0; nt < 4; nt++)
                #pragma unroll
                for (int k = 0; k < 4; k++) acc[mt][nt][k] = 0.0f;

        gemm_tile(sb, acc, lane, wm, wn);

        #pragma unroll
        for (int mt = 0; mt < 4; mt++) {
            #pragma unroll
            for (int nt = 0; nt < 4; nt++) {
                int col = wn * 32 + nt * 8 + (lane & 3) * 2;
                #pragma unroll
                for (int half = 0; half < 2; half++) {
                    int R = base + wm * 64 + mt * 16 + (lane >> 2) + half * 8;
                    float v0 = acc[mt][nt][half * 2];
                    float v1 = acc[mt][nt][half * 2 + 1];
                    int i = R / L, j = R % L;
                    if (m < 3) {
                        float* dst = (m == 0) ? g_q : (m == 1) ? g_k : g_v;
                        float sc = (m == 0) ? (SCALE * LOG2E) : 1.0f;
                        int h = col >> 5, d = col & 31;
                        *(float2*)&dst[(((size_t)i * H + h) * L + j) * DH + d] =
                            make_float2(v0 * sc, v1 * sc);
                    } else {
                        float a0 = v0 + bg[col], a1 = v1 + bg[col + 1];
                        *(float2*)&g_g[(size_t)R * D + col] =
                            make_float2(1.0f / (1.0f + __expf(-a0)),
                                        1.0f / (1.0f + __expf(-a1)));
                    }
                }
            }
        }
    }
}

// ================= kernel 3: tensor-core attention per (i,h) =================
// smem: Q hi/lo fp16 [384 x 32] stride 80B; K hi/lo [320 x 32] stride 80B;
//       V^T hi/lo fp16 [32 x 320] stride 656B; bias [320] fp32
#define AQH 0
#define AQL 30720
#define AKH 61440
#define AKL 87040
#define AVH 112640
#define AVL 133632
#define ABI 154624
#define ATTN_SMEM 155904

__global__ __launch_bounds__(256) void k_attn() {
    char* sm = smx;
    uint32_t sb = smem_u32(sm);

    int blk = blockIdx.x;
    int i = blk >> 2, h = blk & 3;
    int t = threadIdx.x, w = t >> 5, lane = t & 31;

    const float* Qg = g_q + ((size_t)i * H + h) * L * DH;
    const float* Kg = g_k + ((size_t)i * H + h) * L * DH;
    const float* Vg = g_v + ((size_t)i * H + h) * L * DH;

    // stage fp16 hi/lo splits
    for (int idx = t; idx < L * DH; idx += 256) {
        int j = idx >> 5, d = idx & 31;
        float qv = Qg[idx];
        __half qh = __float2half_rn(qv);
        *(__half*)(sm + AQH + j * 80 + d * 2) = qh;
        *(__half*)(sm + AQL + j * 80 + d * 2) = __float2half_rn(qv - __half2float(qh));
        float kv = Kg[idx];
        __half kh = __float2half_rn(kv);
        *(__half*)(sm + AKH + j * 80 + d * 2) = kh;
        *(__half*)(sm + AKL + j * 80 + d * 2) = __float2half_rn(kv - __half2float(kh));
        float vv = Vg[idx];
        __half vh = __float2half_rn(vv);
        *(__half*)(sm + AVH + d * 656 + j * 2) = vh;
        *(__half*)(sm + AVL + d * 656 + j * 2) = __float2half_rn(vv - __half2float(vh));
    }
    // zero-pad Q rows 320..383
    for (int idx = t; idx < 64 * DH; idx += 256) {
        int j = 320 + (idx >> 5), d = idx & 31;
        *(__half*)(sm + AQH + j * 80 + d * 2) = __ushort_as_half(0);
        *(__half*)(sm + AQL + j * 80 + d * 2) = __ushort_as_half(0);
    }
    for (int idx = t; idx < L; idx += 256)
        *(float*)(sm + ABI + idx * 4) = g_bias[(i * H + h) * L + idx];
    __syncthreads();

    if (w == 7) return;   // rows 336..383 are all padding

    int gq = lane >> 3, r8 = lane & 7;
    uint32_t qbase = sb + AQH + (uint32_t)(48 * w + (gq & 1) * 8 + r8) * 80 + (uint32_t)(gq >> 1) * 16;
    uint32_t kbase = sb + AKH + (uint32_t)((gq >> 1) * 8 + r8) * 80 + (uint32_t)(gq & 1) * 16;
    uint32_t vbase = sb + AVH + (uint32_t)((gq >> 1) * 8 + r8) * 656 + (uint32_t)(gq & 1) * 16;
    const float* Bsp = (const float*)(sm + ABI);

    float O[3][4][4];
    float ds[3][2];
    #pragma unroll
    for (int mt = 0; mt < 3; mt++) {
        ds[mt][0] = 0.0f; ds[mt][1] = 0.0f;
        #pragma unroll
        for (int nt = 0; nt < 4; nt++)
            #pragma unroll
            for (int k = 0; k < 4; k++) O[mt][nt][k] = 0.0f;
    }

    #pragma unroll 1
    for (int nb = 0; nb < 5; nb++) {
        // ---- S = Q K^T for 48 rows x 64 keys (3-term fp16 split) ----
        float S[3][8][4];
        #pragma unroll
        for (int mt = 0; mt < 3; mt++)
            #pragma unroll
            for (int nt = 0; nt < 8; nt++)
                #pragma unroll
                for (int k = 0; k < 4; k++) S[mt][nt][k] = 0.0f;

        #pragma unroll
        for (int ks = 0; ks < 2; ks++) {
            uint32_t Ah[3][4], Al[3][4], Bh[4][4], Bl[4][4];
            #pragma unroll
            for (int mt = 0; mt < 3; mt++) {
                ldsm4(Ah[mt], qbase + mt * 1280 + ks * 32);
                ldsm4(Al[mt], qbase + (AQL - AQH) + mt * 1280 + ks * 32);
            }
            #pragma unroll
            for (int nt = 0; nt < 4; nt++) {
                uint32_t ko = (uint32_t)(nb * 64 + nt * 16) * 80 + ks * 32;
                ldsm4(Bh[nt], kbase + ko);
                ldsm4(Bl[nt], kbase + (AKL - AKH) + ko);
            }
            #pragma unroll
            for (int mt = 0; mt < 3; mt++)
                #pragma unroll
                for (int nt = 0; nt < 4; nt++) {
                    mma16816h(S[mt][2 * nt],     Ah[mt], &Bh[nt][0]);
                    mma16816h(S[mt][2 * nt + 1], Ah[mt], &Bh[nt][2]);
                    mma16816h(S[mt][2 * nt],     Ah[mt], &Bl[nt][0]);
                    mma16816h(S[mt][2 * nt + 1], Ah[mt], &Bl[nt][2]);
                    mma16816h(S[mt][2 * nt],     Al[mt], &Bh[nt][0]);
                    mma16816h(S[mt][2 * nt + 1], Al[mt], &Bh[nt][2]);
                }
        }

        // ---- bias + exp2 + repack to A-frags + PV (per 16-key group) ----
        #pragma unroll
        for (int nt = 0; nt < 4; nt++) {
            int c0 = nb * 64 + nt * 16 + 2 * (lane & 3);
            float b00 = Bsp[c0], b01 = Bsp[c0 + 1];
            float b10 = Bsp[c0 + 8], b11 = Bsp[c0 + 9];

            uint32_t PAh[3][4], PAl[3][4];
            #pragma unroll
            for (int mt = 0; mt < 3; mt++) {
                float e00 = ex2f(S[mt][2 * nt][0] + b00);
                float e01 = ex2f(S[mt][2 * nt][1] + b01);
                float e10 = ex2f(S[mt][2 * nt][2] + b00);
                float e11 = ex2f(S[mt][2 * nt][3] + b01);
                float f00 = ex2f(S[mt][2 * nt + 1][0] + b10);
                float f01 = ex2f(S[mt][2 * nt + 1][1] + b11);
                float f10 = ex2f(S[mt][2 * nt + 1][2] + b10);
                float f11 = ex2f(S[mt][2 * nt + 1][3] + b11);
                ds[mt][0] += (e00 + e01) + (f00 + f01);
                ds[mt][1] += (e10 + e11) + (f10 + f11);
                cvth2(e00, e01, PAh[mt][0], PAl[mt][0]);
                cvth2(e10, e11, PAh[mt][1], PAl[mt][1]);
                cvth2(f00, f01, PAh[mt][2], PAl[mt][2]);
                cvth2(f10, f11, PAh[mt][3], PAl[mt][3]);
            }

            uint32_t Vh2[2][4], Vl2[2][4];
            #pragma unroll
            for (int dn = 0; dn < 2; dn++) {
                uint32_t vo = (uint32_t)dn * (16 * 656) + (uint32_t)(nb * 64 + nt * 16) * 2;
                ldsm4(Vh2[dn], vbase + vo);
                ldsm4(Vl2[dn], vbase + (AVL - AVH) + vo);
            }
            #pragma unroll
            for (int mt = 0; mt < 3; mt++)
                #pragma unroll
                for (int dn = 0; dn < 2; dn++) {
                    mma16816h(O[mt][2 * dn],     PAh[mt], &Vh2[dn][0]);
                    mma16816h(O[mt][2 * dn + 1], PAh[mt], &Vh2[dn][2]);
                    mma16816h(O[mt][2 * dn],     PAh[mt], &Vl2[dn][0]);
                    mma16816h(O[mt][2 * dn + 1], PAh[mt], &Vl2[dn][2]);
                    mma16816h(O[mt][2 * dn],     PAl[mt], &Vh2[dn][0]);
                    mma16816h(O[mt][2 * dn + 1], PAl[mt], &Vh2[dn][2]);
                }
        }
    }

    // reduce row-sums across the 4 lanes sharing each row
    #pragma unroll
    for (int mt = 0; mt < 3; mt++)
        #pragma unroll
        for (int rr = 0; rr < 2; rr++) {
            ds[mt][rr] += __shfl_xor_sync(0xffffffffu, ds[mt][rr], 1);
            ds[mt][rr] += __shfl_xor_sync(0xffffffffu, ds[mt][rr], 2);
        }

    // normalize, gate, store
    #pragma unroll
    for (int mt = 0; mt < 3; mt++) {
        float inv0 = __fdividef(1.0f, ds[mt][0]);
        float inv1 = __fdividef(1.0f, ds[mt][1]);
        #pragma unroll
        for (int half = 0; half < 2; half++) {
            int r = 48 * w + mt * 16 + (lane >> 2) + half * 8;
            if (r < L) {
                float inv = half ? inv1 : inv0;
                size_t R = ((size_t)i * L + r) * D + h * DH;
                #pragma unroll
                for (int nt = 0; nt < 4; nt++) {
                    int d = nt * 8 + 2 * (lane & 3);
                    float2 gv = *(const float2*)&g_g[R + d];
                    *(float2*)&g_o[R + d] =
                        make_float2(O[mt][nt][half * 2] * inv * gv.x,
                                    O[mt][nt][half * 2 + 1] * inv * gv.y);
                }
            }
        }
    }
}

// ================= kernel 4: output projection + residual via mma.sync =================
__global__ __launch_bounds__(256) void k_out(const float* __restrict__ Wo,
                                             const float* __restrict__ bo,
                                             const float* __restrict__ pair,
                                             float* __restrict__ out) {
    char* sm = smx;
    uint32_t sb = smem_u32(sm);
    int t = threadIdx.x, w = t >> 5, lane = t & 31;
    int wm = w & 1, wn = w >> 1;
    int base = blockIdx.x * 128;

    stage_tile(g_o + (size_t)base * 128, sm, XH_OFF, XL_OFF, t);
    stage_tile(Wo, sm, WH_OFF, WL_OFF, t);
    __syncthreads();

    float acc[4][4][4];
    #pragma unroll
    for (int mt = 0; mt < 4; mt++)
        #pragma unroll
        for (int nt = 0; nt < 4; nt++)
            #pragma unroll
            for (int k = 0; k < 4; k++) acc[mt][nt][k] = 0.0f;

    gemm_tile(sb, acc, lane, wm, wn);

    #pragma unroll
    for (int mt = 0; mt < 4; mt++) {
        #pragma unroll
        for (int nt = 0; nt < 4; nt++) {
            int col = wn * 32 + nt * 8 + (lane & 3) * 2;
            float2 bov = *(const float2*)&bo[col];
            #pragma unroll
            for (int half = 0; half < 2; half++) {
                size_t R = (size_t)base + wm * 64 + mt * 16 + (lane >> 2) + half * 8;
                float2 pv = *(const float2*)&pair[R * D + col];
                *(float2*)&out[R * D + col] =
                    make_float2(pv.x + acc[mt][nt][half * 2]     + bov.x,
                                pv.y + acc[mt][nt][half * 2 + 1] + bov.y);
            }
        }
    }
}

// ================= launch =================
extern "C" void kernel_launch(void* const* d_in, const int* in_sizes, int n_in,
                              void* d_out, int out_size) {
    const float* pair  = (const float*)d_in[0];
    const float* nw    = (const float*)d_in[1];
    const float* nb    = (const float*)d_in[2];
    const float* Wq    = (const float*)d_in[3];
    const float* Wk    = (const float*)d_in[4];
    const float* Wv    = (const float*)d_in[5];
    const float* Wg    = (const float*)d_in[6];
    const float* bg    = (const float*)d_in[7];
    const float* Wo    = (const float*)d_in[8];
    const float* bo    = (const float*)d_in[9];
    const float* Wb    = (const float*)d_in[10];
    float* out = (float*)d_out;

    static bool attr_set = false;
    if (!attr_set) {
        cudaFuncSetAttribute(k_attn, cudaFuncAttributeMaxDynamicSharedMemorySize, ATTN_SMEM);
        cudaFuncSetAttribute(k_proj, cudaFuncAttributeMaxDynamicSharedMemorySize, GEMM_SMEM);
        cudaFuncSetAttribute(k_out,  cudaFuncAttributeMaxDynamicSharedMemorySize, GEMM_SMEM);
        attr_set = true;
    }

    k_ln_bias<<<NROW, 128>>>(pair, nw, nb, Wb);
    k_proj   <<<NROW / 128, 256, GEMM_SMEM>>>(Wq, Wk, Wv, Wg, bg);
    k_attn   <<<L * H, 256, ATTN_SMEM>>>();
    k_out    <<<NROW / 128, 256, GEMM_SMEM>>>(Wo, bo, pair, out);
}